// round 1
// baseline (speedup 1.0000x reference)
#include <cuda_runtime.h>

#define NB 1024
#define LW 40
#define DIM 128
#define WIN 5
#define NPAIR 370
#define NEG 5
#define NNEG (NPAIR*NEG)   // 1850

__device__ int   g_src[NPAIR];
__device__ int   g_dst[NPAIR];
__device__ float g_partials[NB];

// Build the pair tables in the exact order the reference builds them.
__global__ void init_pairs_kernel() {
    if (threadIdx.x == 0 && blockIdx.x == 0) {
        int c = 0;
        for (int i = 0; i < LW; i++) {
            int lo = i - WIN; if (lo < 0) lo = 0;
            for (int j = lo; j < i; j++) { g_src[c] = j; g_dst[c] = i; c++; }
            int hi = i + 1 + WIN; if (hi > LW) hi = LW;
            for (int j = i + 1; j < hi; j++) { g_src[c] = j; g_dst[c] = i; c++; }
        }
    }
}

__device__ __forceinline__ float warp_sum(float v) {
    #pragma unroll
    for (int o = 16; o > 0; o >>= 1) v += __shfl_xor_sync(0xffffffffu, v, o);
    return v;
}

__global__ __launch_bounds__(256) void walk_kernel(
    const float* __restrict__ node_embed,
    const float* __restrict__ ctx_embed,
    const int*   __restrict__ batch_walk,   // [NB*LW] flat
    const int*   __restrict__ neg_dst_idx)  // [NB*NNEG]
{
    __shared__ float node_s[LW * DIM];   // 20480 B
    __shared__ float ctx_s [LW * DIM];   // 20480 B
    __shared__ int   nid_s [NNEG];       //  7400 B
    __shared__ int   wid_s [LW];         //   160 B
    __shared__ float wsum  [8];          //    32 B  -> 48552 B total

    const int b   = blockIdx.x;
    const int tid = threadIdx.x;

    if (tid < LW) wid_s[tid] = batch_walk[b * LW + tid];
    __syncthreads();

    // Gather this walk's node + context embedding rows into SMEM (coalesced float4).
    for (int t = tid; t < LW * 32; t += 256) {
        int row = t >> 5, q = t & 31;
        int base = wid_s[row] * DIM + q * 4;
        *(float4*)(node_s + row * DIM + q * 4) = *(const float4*)(node_embed + base);
        *(float4*)(ctx_s  + row * DIM + q * 4) = *(const float4*)(ctx_embed  + base);
    }
    // Resolve the double indirection for all negatives up front.
    const int* nd = neg_dst_idx + b * NNEG;
    for (int n = tid; n < NNEG; n += 256)
        nid_s[n] = batch_walk[nd[n]];
    __syncthreads();

    const int warp = tid >> 5, lane = tid & 31;
    float acc = 0.f;

    // Warp-per-pair: 1 positive dot + its 5 negatives.
    for (int p = warp; p < NPAIR; p += 8) {
        const int s = g_src[p], d = g_dst[p];

        float4 a = *(const float4*)(node_s + s * DIM + lane * 4);
        float4 c = *(const float4*)(ctx_s  + d * DIM + lane * 4);
        float v = warp_sum(a.x * c.x + a.y * c.y + a.z * c.z + a.w * c.w);
        v = fminf(fmaxf(v, -6.f), 6.f);
        acc += log1pf(expf(-v));                      // -log_sigmoid(v)

        // Negatives: node side = ctx-dst row of this pair (SMEM),
        // ctx side = global gather (L2-resident). 5 independent LDG.128 for MLP.
        float4 a2 = *(const float4*)(node_s + d * DIM + lane * 4);
        float4 cg[NEG];
        #pragma unroll
        for (int k = 0; k < NEG; k++) {
            int nid = nid_s[p * NEG + k];
            cg[k] = *(const float4*)(ctx_embed + nid * DIM + lane * 4);
        }
        #pragma unroll
        for (int k = 0; k < NEG; k++) {
            float u = warp_sum(a2.x * cg[k].x + a2.y * cg[k].y +
                               a2.z * cg[k].z + a2.w * cg[k].w);
            u = fminf(fmaxf(u, -6.f), 6.f);
            acc += log1pf(expf(u));                   // -log_sigmoid(-u)
        }
    }

    if (lane == 0) wsum[warp] = acc;
    __syncthreads();
    if (tid == 0) {
        float s = 0.f;
        #pragma unroll
        for (int w = 0; w < 8; w++) s += wsum[w];
        g_partials[b] = s;
    }
}

__global__ void final_reduce_kernel(float* __restrict__ out) {
    __shared__ float sm[256];
    float v = 0.f;
    for (int i = threadIdx.x; i < NB; i += 256) v += g_partials[i];
    sm[threadIdx.x] = v;
    __syncthreads();
    for (int s = 128; s > 0; s >>= 1) {
        if (threadIdx.x < s) sm[threadIdx.x] += sm[threadIdx.x + s];
        __syncthreads();
    }
    if (threadIdx.x == 0)
        out[0] = sm[0] * (1.0f / (float)(NB * NPAIR));
}

extern "C" void kernel_launch(void* const* d_in, const int* in_sizes, int n_in,
                              void* d_out, int out_size) {
    const float* node_embed  = (const float*)d_in[0];
    const float* ctx_embed   = (const float*)d_in[1];
    const int*   batch_walk  = (const int*)d_in[2];
    const int*   neg_dst_idx = (const int*)d_in[3];
    float*       out         = (float*)d_out;

    init_pairs_kernel<<<1, 32>>>();
    walk_kernel<<<NB, 256>>>(node_embed, ctx_embed, batch_walk, neg_dst_idx);
    final_reduce_kernel<<<1, 256>>>(out);
}

// round 3
// speedup vs baseline: 1.7329x; 1.7329x over previous
#include <cuda_runtime.h>

#define NB 1024
#define LW 40
#define DIM 128
#define WIN 5
#define NPAIR 370
#define NEG 5
#define NNEG (NPAIR*NEG)      // 1850
#define NSC  (NPAIR + NNEG)   // 2220 scores per walk

__device__ float g_partials[NB];

__device__ __forceinline__ float dot4(float4 a, float4 b) {
    return a.x * b.x + a.y * b.y + a.z * b.z + a.w * b.w;
}

__global__ __launch_bounds__(256) void walk_kernel(
    const float* __restrict__ node_embed,
    const float* __restrict__ ctx_embed,
    const int*   __restrict__ batch_walk,   // [NB*LW] flat
    const int*   __restrict__ neg_dst_idx)  // [NB*NNEG]
{
    __shared__ float          node_s[LW * DIM];  // 20480 B
    __shared__ float          ctx_s [LW * DIM];  // 20480 B
    __shared__ int            nid_s [NNEG];      //  7400 B
    __shared__ unsigned short pair_s[NPAIR];     //   740 B
    __shared__ float          wsum  [8];         // -> 49132 B total

    const int b   = blockIdx.x;
    const int tid = threadIdx.x;

    // Build the (src,dst) pair table in reference order (closed-form offsets).
    if (tid < LW) {
        const int i = tid;
        int cum;
        if (i <= 5)       cum = 5 * i + (i * (i - 1)) / 2;
        else if (i <= 35) cum = 35 + 10 * (i - 5);
        else { int m = i - 35; cum = 335 + 9 * m - (m * (m - 1)) / 2; }
        int lo = i - WIN; if (lo < 0) lo = 0;
        int hi = i + 1 + WIN; if (hi > LW) hi = LW;
        for (int j = lo; j < i; j++)     pair_s[cum++] = (unsigned short)(j | (i << 8));
        for (int j = i + 1; j < hi; j++) pair_s[cum++] = (unsigned short)(j | (i << 8));
    }

    // Gather this walk's node + context rows into SMEM (coalesced float4).
    for (int t = tid; t < LW * 32; t += 256) {
        int row = t >> 5, q = t & 31;
        int id = __ldg(batch_walk + b * LW + row);      // L1 broadcast hit
        int base = id * DIM + q * 4;
        *(float4*)(node_s + row * DIM + q * 4) = *(const float4*)(node_embed + base);
        *(float4*)(ctx_s  + row * DIM + q * 4) = *(const float4*)(ctx_embed  + base);
    }
    // Resolve the double indirection for all negatives up front.
    const int* nd = neg_dst_idx + b * NNEG;
    for (int n = tid; n < NNEG; n += 256)
        nid_s[n] = __ldg(batch_walk + nd[n]);
    __syncthreads();

    const int warp = tid >> 5, lane = tid & 31;
    const int grp  = lane >> 3, j = lane & 7;     // 4 groups of 8 lanes / warp

    float acc = 0.f;

    // Each 8-lane group computes one score; a warp does 4 scores/iteration.
    for (int q0 = warp * 4; q0 < NSC; q0 += 32) {
        const int q = q0 + grp;
        const bool valid = (q < NSC);

        float partial = 0.f;
        float sign = 1.f;
        if (valid && q < NPAIR) {
            // positive pair
            const int pk = pair_s[q];
            const int s = pk & 0xff, d = pk >> 8;
            const float4* A = (const float4*)(node_s + s * DIM);
            const float4* C = (const float4*)(ctx_s  + d * DIM);
            #pragma unroll
            for (int t = 0; t < 4; t++)
                partial += dot4(A[j + 8 * t], C[j + 8 * t]);
            sign = -1.f;                                  // softplus(-v)
        } else if (valid) {
            // negative: node side = pair's dst row (SMEM), ctx side = global (L2)
            const int n = q - NPAIR;
            const int p = n / 5;
            const int d = pair_s[p] >> 8;
            const float4* A = (const float4*)(node_s + d * DIM);
            const float4* C = (const float4*)(ctx_embed + nid_s[n] * DIM);
            #pragma unroll
            for (int t = 0; t < 4; t++)
                partial += dot4(A[j + 8 * t], C[j + 8 * t]);
        }

        // 3-step butterfly reduces all 4 group-dots at once.
        partial += __shfl_xor_sync(0xffffffffu, partial, 4);
        partial += __shfl_xor_sync(0xffffffffu, partial, 2);
        partial += __shfl_xor_sync(0xffffffffu, partial, 1);

        float x = valid ? sign * fminf(fmaxf(partial, -6.f), 6.f) : -1e30f;
        float sp = __logf(1.f + __expf(x));               // one softplus / 4 scores
        if (j == 0) acc += sp;
    }

    // Warp sum (only lanes 0,8,16,24 carry nonzero acc).
    #pragma unroll
    for (int o = 16; o > 0; o >>= 1) acc += __shfl_xor_sync(0xffffffffu, acc, o);
    if (lane == 0) wsum[warp] = acc;
    __syncthreads();
    if (tid == 0) {
        float s = 0.f;
        #pragma unroll
        for (int w = 0; w < 8; w++) s += wsum[w];
        g_partials[b] = s;
    }
}

__global__ void final_reduce_kernel(float* __restrict__ out) {
    __shared__ float sm[256];
    float v = 0.f;
    for (int i = threadIdx.x; i < NB; i += 256) v += g_partials[i];
    sm[threadIdx.x] = v;
    __syncthreads();
    for (int s = 128; s > 0; s >>= 1) {
        if (threadIdx.x < s) sm[threadIdx.x] += sm[threadIdx.x + s];
        __syncthreads();
    }
    if (threadIdx.x == 0)
        out[0] = sm[0] * (1.0f / (float)(NB * NPAIR));
}

extern "C" void kernel_launch(void* const* d_in, const int* in_sizes, int n_in,
                              void* d_out, int out_size) {
    const float* node_embed  = (const float*)d_in[0];
    const float* ctx_embed   = (const float*)d_in[1];
    const int*   batch_walk  = (const int*)d_in[2];
    const int*   neg_dst_idx = (const int*)d_in[3];
    float*       out         = (float*)d_out;

    walk_kernel<<<NB, 256>>>(node_embed, ctx_embed, batch_walk, neg_dst_idx);
    final_reduce_kernel<<<1, 256>>>(out);
}